// round 15
// baseline (speedup 1.0000x reference)
#include <cuda_runtime.h>

#define HH 64
#define WW 64
#define HWSZ 4096
#define CCH 64

// ---- device scratch (allocation-free rule) ----
__device__ float g_off [2 * 296 * HWSZ];
__device__ float g_tmp [4 * CCH * 2 * HWSZ];
__device__ float g_part[8 * 2 * 128 * HWSZ];
__device__ float g_wt  [524288];
__device__ float2 g_xi [2 * 64 * HWSZ];
__device__ float2 g_t0ai[2 * 32 * HWSZ];
__device__ float2 g_t0bi[2 * 32 * HWSZ];

// ---- packed f32x2 helpers ----
__device__ __forceinline__ unsigned long long pk2(float lo, float hi) {
    unsigned long long r;
    asm("mov.b64 %0, {%1, %2};" : "=l"(r) : "f"(lo), "f"(hi));
    return r;
}
__device__ __forceinline__ void fma2(unsigned long long& d, unsigned long long a,
                                     unsigned long long b) {
    asm("fma.rn.f32x2 %0, %1, %2, %3;" : "=l"(d) : "l"(a), "l"(b), "l"(d));
}
__device__ __forceinline__ void unpk2(unsigned long long v, float& lo, float& hi) {
    asm("mov.b64 {%0, %1}, %2;" : "=f"(lo), "=f"(hi) : "l"(v));
}
__device__ __forceinline__ unsigned long long mul2(unsigned long long a,
                                                   unsigned long long b) {
    unsigned long long r;
    asm("mul.rn.f32x2 %0, %1, %2;" : "=l"(r) : "l"(a), "l"(b));
    return r;
}

// ---------------------------------------------------------------------------
// Fused weight transpose: wv[O][64][K][K] -> wt[tap][O]
// ---------------------------------------------------------------------------
__global__ void wtrans_all(const float* __restrict__ w0,
                           const float* __restrict__ w1,
                           const float* __restrict__ w2,
                           const float* __restrict__ w3,
                           float* __restrict__ wt)
{
    int idx = blockIdx.x * 256 + threadIdx.x;
    const int n0 = 18 * 576, n1 = 50 * 1600, n2 = 50 * 1600, n3 = 98 * 3136;
    const float* src; int O, taps; float* dst;
    if (idx < n0)                { src = w0; O = 18; taps = 576;  dst = wt; }
    else if ((idx -= n0) < n1)   { src = w1; O = 50; taps = 1600; dst = wt + n0; }
    else if ((idx -= n1) < n2)   { src = w2; O = 50; taps = 1600; dst = wt + n0 + n1; }
    else if ((idx -= n2) < n3)   { src = w3; O = 98; taps = 3136; dst = wt + n0 + n1 + n2; }
    else return;
    int o = idx / taps;
    int t = idx - o * taps;
    dst[(size_t)t * O + o] = src[idx];
}

// ---------------------------------------------------------------------------
// xpack: x[b][128][hw] -> xi[b][64 pairs][hw]{c0,c1}.  grid (16,64,2).
// ---------------------------------------------------------------------------
__global__ void xpack_kernel(const float* __restrict__ x, float2* __restrict__ xi)
{
    const int p  = blockIdx.x * 256 + threadIdx.x;
    const int c2 = blockIdx.y;
    const int b  = blockIdx.z;
    const float* xp = x + ((size_t)b * 128 + 2 * c2) * HWSZ + p;
    xi[((size_t)b * 64 + c2) * HWSZ + p] = make_float2(xp[0], xp[HWSZ]);
}

// ---------------------------------------------------------------------------
// Offset conv implicit GEMM, f32x2 (R4 form + og-skip). Proven best.
// Block 256 thr; tile 32 oc x (4 rows x 64 cols); per-thread 8 oc x 2 f32x2.
// grid = (16 hblk, ceil(O/32), 2*ns). Partials [sp][b][O][HWSZ] (no bias).
// ---------------------------------------------------------------------------
template<int K, int DIL, int PAD>
__global__ void offconv_gemm(const float* __restrict__ src, int srcC, int coff,
                             const float* __restrict__ wt, int O, int ns,
                             float* __restrict__ part)
{
    constexpr int KK     = K * K;
    constexpr int WPAD   = 64 + 2 * PAD;
    constexpr int ROWS_X = 4 + (K - 1) * DIL;

    __shared__ float  XS[ROWS_X][WPAD];
    __shared__ float2 WS2[KK][32];

    const int tid  = threadIdx.x;
    const int lane = tid & 63;
    const int og   = tid >> 6;
    const int h0   = blockIdx.x * 4;
    const int o0   = blockIdx.y * 32;
    const int b    = blockIdx.z / ns;
    const int sp   = blockIdx.z % ns;
    const int cchunk = CCH / ns;
    const int cbeg = sp * cchunk;
    const int cend = cbeg + cchunk;

    const bool active = (o0 + og * 8) < O;

    unsigned long long acc[8][2];
    #pragma unroll
    for (int oc = 0; oc < 8; ++oc) { acc[oc][0] = 0ull; acc[oc][1] = 0ull; }

    for (int c = cbeg; c < cend; ++c) {
        const float* sc = src + (((size_t)b * srcC + coff + c) << 12);
        const float* wc = wt + (size_t)c * KK * O;
        __syncthreads();
        for (int idx = tid; idx < ROWS_X * WPAD; idx += 256) {
            const int rr  = idx / WPAD;
            const int s   = idx - rr * WPAD;
            const int yy  = h0 - PAD + rr;
            const int col = s - PAD;
            float v = 0.f;
            if ((unsigned)yy < 64u && (unsigned)col < 64u) v = sc[yy * 64 + col];
            XS[rr][s] = v;
        }
        for (int idx = tid; idx < KK * 32; idx += 256) {
            const int tap = idx >> 5;
            const int oc  = idx & 31;
            const int o   = o0 + oc;
            const float w = (o < O) ? wc[tap * O + o] : 0.f;
            WS2[tap][oc] = make_float2(w, w);
        }
        __syncthreads();

        if (active) {
            #pragma unroll 1
            for (int i = 0; i < K; ++i) {
                const int ri = i * DIL;
                #pragma unroll
                for (int j = 0; j < K; ++j) {
                    const ulonglong2* wrow = (const ulonglong2*)&WS2[i * K + j][og * 8];
                    const ulonglong2 wq0 = wrow[0];
                    const ulonglong2 wq1 = wrow[1];
                    const ulonglong2 wq2 = wrow[2];
                    const ulonglong2 wq3 = wrow[3];
                    const int sx = lane + j * DIL;
                    const unsigned long long xa = pk2(XS[ri + 0][sx], XS[ri + 1][sx]);
                    const unsigned long long xb = pk2(XS[ri + 2][sx], XS[ri + 3][sx]);
                    fma2(acc[0][0], wq0.x, xa);  fma2(acc[0][1], wq0.x, xb);
                    fma2(acc[1][0], wq0.y, xa);  fma2(acc[1][1], wq0.y, xb);
                    fma2(acc[2][0], wq1.x, xa);  fma2(acc[2][1], wq1.x, xb);
                    fma2(acc[3][0], wq1.y, xa);  fma2(acc[3][1], wq1.y, xb);
                    fma2(acc[4][0], wq2.x, xa);  fma2(acc[4][1], wq2.x, xb);
                    fma2(acc[5][0], wq2.y, xa);  fma2(acc[5][1], wq2.y, xb);
                    fma2(acc[6][0], wq3.x, xa);  fma2(acc[6][1], wq3.x, xb);
                    fma2(acc[7][0], wq3.y, xa);  fma2(acc[7][1], wq3.y, xb);
                }
            }
        }
    }

    float* pb = part + (((size_t)sp * 2 + b) * O) * HWSZ;
    #pragma unroll
    for (int oc = 0; oc < 8; ++oc) {
        const int o = o0 + og * 8 + oc;
        if (o < O) {
            float r0, r1, r2, r3;
            unpk2(acc[oc][0], r0, r1);
            unpk2(acc[oc][1], r2, r3);
            float* po = pb + (size_t)o * HWSZ + h0 * 64 + lane;
            po[0]   = r0;
            po[64]  = r1;
            po[128] = r2;
            po[192] = r3;
        }
    }
}

// ---------------------------------------------------------------------------
// combine (MLP unrolled, 128-thr blocks): load all NS slabs, then sum.
// grid (8, O, 2), block 128.
// ---------------------------------------------------------------------------
template<int NS>
__global__ void combine_kernel(const float* __restrict__ part,
                               const float* __restrict__ bias,
                               int O, float* __restrict__ out)
{
    const int p = blockIdx.x * 128 + threadIdx.x;
    const int o = blockIdx.y;
    const int b = blockIdx.z;

    float4 v[NS];
    #pragma unroll
    for (int sp = 0; sp < NS; ++sp)
        v[sp] = ((const float4*)part)[(((size_t)sp * 2 + b) * O + o) * 1024 + p];

    const float bs = bias[o];
    float4 s = make_float4(bs, bs, bs, bs);
    #pragma unroll
    for (int sp = 0; sp < NS; ++sp) {
        s.x += v[sp].x; s.y += v[sp].y; s.z += v[sp].z; s.w += v[sp].w;
    }
    ((float4*)out)[((size_t)b * O + o) * 1024 + p] = s;
}

// ---------------------------------------------------------------------------
// Deformable depthwise conv over channel PAIRS with interleaved float2
// gathers. Block 256 thr; grid (16, 32, 2) = 1024 blocks. (R10, proven)
// ---------------------------------------------------------------------------
template<int KS, int DIL, int PAD>
__global__ void deform_i(const float2* __restrict__ xin, int cstride, int coffp,
                         const float* __restrict__ off,
                         const float* __restrict__ dw,
                         float* __restrict__ out, float2* __restrict__ outi)
{
    constexpr int K = KS * KS;
    __shared__ float sdw[2][K];

    const int tid = threadIdx.x;
    const int w   = tid & 63;
    const int r   = tid >> 6;
    const int h   = blockIdx.x * 4 + r;
    const int cg  = blockIdx.y;
    const int b   = blockIdx.z;

    if (tid < 2 * K) sdw[tid / K][tid % K] = dw[(cg * 2 + tid / K) * K + tid % K];
    __syncthreads();

    const float2* xr = xin + ((size_t)b * cstride + coffp + cg) * HWSZ;
    const float*  ob = off + (size_t)b * (2 * K) * HWSZ + h * WW + w;

    float acc0 = 0.f, acc1 = 0.f;

    #pragma unroll 2
    for (int kidx = 0; kidx < K; ++kidx) {
        const float oy = ob[(2 * kidx)     * HWSZ];
        const float ox = ob[(2 * kidx + 1) * HWSZ];
        const float py = oy + (float)(h - PAD + (kidx / KS) * DIL);
        const float px = ox + (float)(w - PAD + (kidx % KS) * DIL);
        const int   y0 = __float2int_rd(py);
        const int   x0 = __float2int_rd(px);
        const float ly = py - (float)y0;
        const float lx = px - (float)x0;

        const float hyM = ((unsigned)y0       < 64u) ? (1.f - ly) : 0.f;
        const float lyM = ((unsigned)(y0 + 1) < 64u) ? ly         : 0.f;
        const float hxM = ((unsigned)x0       < 64u) ? (1.f - lx) : 0.f;
        const float lxM = ((unsigned)(x0 + 1) < 64u) ? lx         : 0.f;

        const float w00 = hyM * hxM;
        const float w01 = hyM * lxM;
        const float w10 = lyM * hxM;
        const float w11 = lyM * lxM;

        const int i00 = (y0 * 64 + x0) & 4095;
        const int i01 = (i00 + 1)  & 4095;
        const int i10 = (i00 + 64) & 4095;
        const int i11 = (i00 + 65) & 4095;

        const float2 v00 = xr[i00];
        const float2 v01 = xr[i01];
        const float2 v10 = xr[i10];
        const float2 v11 = xr[i11];

        float va = v00.x * w00;
        va = fmaf(v01.x, w01, va);
        va = fmaf(v10.x, w10, va);
        va = fmaf(v11.x, w11, va);
        acc0 = fmaf(va, sdw[0][kidx], acc0);

        float vb = v00.y * w00;
        vb = fmaf(v01.y, w01, vb);
        vb = fmaf(v10.y, w10, vb);
        vb = fmaf(v11.y, w11, vb);
        acc1 = fmaf(vb, sdw[1][kidx], acc1);
    }

    const int p = h * WW + w;
    float* po = out + ((size_t)b * CCH + cg * 2) * HWSZ + p;
    po[0]    = acc0;
    po[HWSZ] = acc1;
    if (outi)
        outi[((size_t)b * 32 + cg) * HWSZ + p] = make_float2(acc0, acc1);
}

// ---------------------------------------------------------------------------
// 1x1 conv + gate, 2 outputs per block (R13, proven).
// grid (8, 32, 2) = 512 blocks, block 256 (512 px).
// ---------------------------------------------------------------------------
__global__ void conv1x1_gate2(const float* __restrict__ in,
                              const float* __restrict__ wv,
                              const float* __restrict__ bias,
                              const float* __restrict__ x,
                              int xcoff, float* __restrict__ out)
{
    __shared__ float2 wsm[CCH][2];
    const int tid = threadIdx.x;
    const int o0  = blockIdx.y * 2;
    const int b   = blockIdx.z;
    const int px0 = blockIdx.x * 512 + tid * 2;

    for (int idx = tid; idx < CCH * 2; idx += 256) {
        const int c = idx >> 1;
        const int o = idx & 1;
        const float w_ = wv[(o0 + o) * CCH + c];
        wsm[c][o] = make_float2(w_, w_);
    }
    __syncthreads();

    unsigned long long a0 = pk2(bias[o0],     bias[o0]);
    unsigned long long a1 = pk2(bias[o0 + 1], bias[o0 + 1]);

    const float* ib = in + (size_t)b * CCH * HWSZ + px0;
    #pragma unroll 8
    for (int c = 0; c < CCH; ++c) {
        const unsigned long long iv = *(const unsigned long long*)(ib + (size_t)c * HWSZ);
        const ulonglong2 w2 = *(const ulonglong2*)&wsm[c][0];
        fma2(a0, w2.x, iv);
        fma2(a1, w2.y, iv);
    }

    const size_t oi0 = ((size_t)b * 128 + xcoff + o0) * HWSZ + px0;
    const unsigned long long xv0 = *(const unsigned long long*)(x + oi0);
    const unsigned long long xv1 = *(const unsigned long long*)(x + oi0 + HWSZ);
    *(unsigned long long*)(out + oi0)        = mul2(a0, xv0);
    *(unsigned long long*)(out + oi0 + HWSZ) = mul2(a1, xv1);
}

// ---------------------------------------------------------------------------
extern "C" void kernel_launch(void* const* d_in, const int* in_sizes, int n_in,
                              void* d_out, int out_size)
{
    const float* x          = (const float*)d_in[0];
    const float* cv0_off_w  = (const float*)d_in[1];
    const float* cv0_off_b  = (const float*)d_in[2];
    const float* cv0_w      = (const float*)d_in[3];
    const float* cvs_off_w  = (const float*)d_in[4];
    const float* cvs_off_b  = (const float*)d_in[5];
    const float* cvs_w      = (const float*)d_in[6];
    const float* c0_off_w   = (const float*)d_in[7];
    const float* c0_off_b   = (const float*)d_in[8];
    const float* c0_w       = (const float*)d_in[9];
    const float* cs_off_w   = (const float*)d_in[10];
    const float* cs_off_b   = (const float*)d_in[11];
    const float* cs_w       = (const float*)d_in[12];
    const float* conv1_w    = (const float*)d_in[13];
    const float* conv1_b    = (const float*)d_in[14];
    const float* conv2_w    = (const float*)d_in[15];
    const float* conv2_b    = (const float*)d_in[16];
    float* out = (float*)d_out;

    static cudaStream_t s2 = nullptr;
    static cudaEvent_t evRoot = nullptr, evW = nullptr, evX = nullptr, evJoin = nullptr;
    if (!s2) {
        cudaStreamCreateWithFlags(&s2, cudaStreamNonBlocking);
        cudaEventCreateWithFlags(&evRoot, cudaEventDisableTiming);
        cudaEventCreateWithFlags(&evW,    cudaEventDisableTiming);
        cudaEventCreateWithFlags(&evX,    cudaEventDisableTiming);
        cudaEventCreateWithFlags(&evJoin, cudaEventDisableTiming);
    }

    float *offb, *tmp, *part, *wt;
    float2 *xi, *t0ai, *t0bi;
    cudaGetSymbolAddress((void**)&offb, g_off);
    cudaGetSymbolAddress((void**)&tmp,  g_tmp);
    cudaGetSymbolAddress((void**)&part, g_part);
    cudaGetSymbolAddress((void**)&wt,   g_wt);
    cudaGetSymbolAddress((void**)&xi,   g_xi);
    cudaGetSymbolAddress((void**)&t0ai, g_t0ai);
    cudaGetSymbolAddress((void**)&t0bi, g_t0bi);

    float* off0  = offb;
    float* off1  = offb + (size_t)2 * 100 * HWSZ;
    float* t0a   = tmp;
    float* t1a   = tmp + (size_t)1 * CCH * 2 * HWSZ;
    float* t0b   = tmp + (size_t)2 * CCH * 2 * HWSZ;
    float* t1b   = tmp + (size_t)3 * CCH * 2 * HWSZ;
    float* part0 = part;
    float* part1 = part + (size_t)4 * 1024 * 1024;

    const int taps3 = 576, taps5 = 1600, taps7 = 3136;
    float* wt_cv0 = wt;
    float* wt_cvs = wt_cv0 + 18 * taps3;
    float* wt_c0  = wt_cvs + 50 * taps5;
    float* wt_cs  = wt_c0  + 50 * taps5;

    dim3 b256(256), b128(128);

    // legal fork: s2 joins capture via event recorded in origin stream FIRST
    cudaEventRecord(evRoot, 0);
    cudaStreamWaitEvent(s2, evRoot, 0);

    // parallel prologue: wtrans on s0 || xpack on s2
    const int n_all = 18 * taps3 + 50 * taps5 + 50 * taps5 + 98 * taps7;
    wtrans_all<<<(n_all + 255) / 256, b256>>>(cv0_off_w, cvs_off_w, c0_off_w, cs_off_w, wt);
    cudaEventRecord(evW, 0);
    xpack_kernel<<<dim3(16, 64, 2), b256, 0, s2>>>(x, xi);
    cudaEventRecord(evX, s2);
    cudaStreamWaitEvent(0, evX, 0);   // branch0 (s0) needs xi
    cudaStreamWaitEvent(s2, evW, 0);  // branch1 (s2) needs wt

    // ---- Branch 0 (stream 0): channels [0,64) ----
    offconv_gemm<3,1,1><<<dim3(16, 1, 2 * 8), b256>>>(x, 128, 0, wt_cv0, 18, 8, part0);
    combine_kernel<8><<<dim3(8, 18, 2), b128>>>(part0, cv0_off_b, 18, off0);
    deform_i<3,1,1><<<dim3(16, 32, 2), b256>>>(xi, 64, 0, off0, cv0_w, t0a, t0ai);

    offconv_gemm<5,3,6><<<dim3(16, 2, 2 * 8), b256>>>(t0a, 64, 0, wt_cvs, 50, 8, part0);
    combine_kernel<8><<<dim3(8, 50, 2), b128>>>(part0, cvs_off_b, 50, off0);
    deform_i<5,3,6><<<dim3(16, 32, 2), b256>>>(t0ai, 32, 0, off0, cvs_w, t1a, nullptr);

    conv1x1_gate2<<<dim3(8, 32, 2), b256>>>(t1a, conv1_w, conv1_b, x, 0, out);

    // ---- Branch 1 (stream s2): channels [64,128) ----
    offconv_gemm<5,1,2><<<dim3(16, 2, 2 * 8), b256, 0, s2>>>(x, 128, 64, wt_c0, 50, 8, part1);
    combine_kernel<8><<<dim3(8, 50, 2), b128, 0, s2>>>(part1, c0_off_b, 50, off1);
    deform_i<5,1,2><<<dim3(16, 32, 2), b256, 0, s2>>>(xi, 64, 32, off1, c0_w, t0b, t0bi);

    offconv_gemm<7,3,9><<<dim3(16, 4, 2 * 4), b256, 0, s2>>>(t0b, 64, 0, wt_cs, 98, 4, part1);
    combine_kernel<4><<<dim3(8, 98, 2), b128, 0, s2>>>(part1, cs_off_b, 98, off1);
    deform_i<7,3,9><<<dim3(16, 32, 2), b256, 0, s2>>>(t0bi, 32, 0, off1, cs_w, t1b, nullptr);

    conv1x1_gate2<<<dim3(8, 32, 2), b256, 0, s2>>>(t1b, conv2_w, conv2_b, x, 64, out);

    cudaEventRecord(evJoin, s2);
    cudaStreamWaitEvent(0, evJoin, 0);
}

// round 16
// speedup vs baseline: 1.0583x; 1.0583x over previous
#include <cuda_runtime.h>

#define HH 64
#define WW 64
#define HWSZ 4096
#define CCH 64

// ---- device scratch (allocation-free rule) ----
__device__ float g_off [2 * 296 * HWSZ];
__device__ float g_tmp [4 * CCH * 2 * HWSZ];
__device__ float g_part[8 * 2 * 128 * HWSZ];
__device__ float g_wt  [524288];
__device__ float2 g_xi [2 * 64 * HWSZ];
__device__ float2 g_t0ai[2 * 32 * HWSZ];
__device__ float2 g_t0bi[2 * 32 * HWSZ];

// ---- packed f32x2 helpers ----
__device__ __forceinline__ unsigned long long pk2(float lo, float hi) {
    unsigned long long r;
    asm("mov.b64 %0, {%1, %2};" : "=l"(r) : "f"(lo), "f"(hi));
    return r;
}
__device__ __forceinline__ void fma2(unsigned long long& d, unsigned long long a,
                                     unsigned long long b) {
    asm("fma.rn.f32x2 %0, %1, %2, %3;" : "=l"(d) : "l"(a), "l"(b), "l"(d));
}
__device__ __forceinline__ void unpk2(unsigned long long v, float& lo, float& hi) {
    asm("mov.b64 {%0, %1}, %2;" : "=f"(lo), "=f"(hi) : "l"(v));
}
__device__ __forceinline__ unsigned long long mul2(unsigned long long a,
                                                   unsigned long long b) {
    unsigned long long r;
    asm("mul.rn.f32x2 %0, %1, %2;" : "=l"(r) : "l"(a), "l"(b));
    return r;
}

// ---------------------------------------------------------------------------
// Fused weight transpose: wv[O][64][K][K] -> wt[tap][O]
// ---------------------------------------------------------------------------
__global__ void wtrans_all(const float* __restrict__ w0,
                           const float* __restrict__ w1,
                           const float* __restrict__ w2,
                           const float* __restrict__ w3,
                           float* __restrict__ wt)
{
    int idx = blockIdx.x * 256 + threadIdx.x;
    const int n0 = 18 * 576, n1 = 50 * 1600, n2 = 50 * 1600, n3 = 98 * 3136;
    const float* src; int O, taps; float* dst;
    if (idx < n0)                { src = w0; O = 18; taps = 576;  dst = wt; }
    else if ((idx -= n0) < n1)   { src = w1; O = 50; taps = 1600; dst = wt + n0; }
    else if ((idx -= n1) < n2)   { src = w2; O = 50; taps = 1600; dst = wt + n0 + n1; }
    else if ((idx -= n2) < n3)   { src = w3; O = 98; taps = 3136; dst = wt + n0 + n1 + n2; }
    else return;
    int o = idx / taps;
    int t = idx - o * taps;
    dst[(size_t)t * O + o] = src[idx];
}

// ---------------------------------------------------------------------------
// xpack: x[b][128][hw] -> xi[b][64 pairs][hw]{c0,c1}.  grid (16,64,2).
// ---------------------------------------------------------------------------
__global__ void xpack_kernel(const float* __restrict__ x, float2* __restrict__ xi)
{
    const int p  = blockIdx.x * 256 + threadIdx.x;
    const int c2 = blockIdx.y;
    const int b  = blockIdx.z;
    const float* xp = x + ((size_t)b * 128 + 2 * c2) * HWSZ + p;
    xi[((size_t)b * 64 + c2) * HWSZ + p] = make_float2(xp[0], xp[HWSZ]);
}

// ---------------------------------------------------------------------------
// Offset conv implicit GEMM, f32x2 (R4 form + og-skip). Proven best.
// Block 256 thr; tile 32 oc x (4 rows x 64 cols); per-thread 8 oc x 2 f32x2.
// grid = (16 hblk, ceil(O/32), 2*ns). Partials [sp][b][O][HWSZ] (no bias).
// ---------------------------------------------------------------------------
template<int K, int DIL, int PAD>
__global__ void offconv_gemm(const float* __restrict__ src, int srcC, int coff,
                             const float* __restrict__ wt, int O, int ns,
                             float* __restrict__ part)
{
    constexpr int KK     = K * K;
    constexpr int WPAD   = 64 + 2 * PAD;
    constexpr int ROWS_X = 4 + (K - 1) * DIL;

    __shared__ float  XS[ROWS_X][WPAD];
    __shared__ float2 WS2[KK][32];

    const int tid  = threadIdx.x;
    const int lane = tid & 63;
    const int og   = tid >> 6;
    const int h0   = blockIdx.x * 4;
    const int o0   = blockIdx.y * 32;
    const int b    = blockIdx.z / ns;
    const int sp   = blockIdx.z % ns;
    const int cchunk = CCH / ns;
    const int cbeg = sp * cchunk;
    const int cend = cbeg + cchunk;

    const bool active = (o0 + og * 8) < O;

    unsigned long long acc[8][2];
    #pragma unroll
    for (int oc = 0; oc < 8; ++oc) { acc[oc][0] = 0ull; acc[oc][1] = 0ull; }

    for (int c = cbeg; c < cend; ++c) {
        const float* sc = src + (((size_t)b * srcC + coff + c) << 12);
        const float* wc = wt + (size_t)c * KK * O;
        __syncthreads();
        for (int idx = tid; idx < ROWS_X * WPAD; idx += 256) {
            const int rr  = idx / WPAD;
            const int s   = idx - rr * WPAD;
            const int yy  = h0 - PAD + rr;
            const int col = s - PAD;
            float v = 0.f;
            if ((unsigned)yy < 64u && (unsigned)col < 64u) v = sc[yy * 64 + col];
            XS[rr][s] = v;
        }
        for (int idx = tid; idx < KK * 32; idx += 256) {
            const int tap = idx >> 5;
            const int oc  = idx & 31;
            const int o   = o0 + oc;
            const float w = (o < O) ? wc[tap * O + o] : 0.f;
            WS2[tap][oc] = make_float2(w, w);
        }
        __syncthreads();

        if (active) {
            #pragma unroll 1
            for (int i = 0; i < K; ++i) {
                const int ri = i * DIL;
                #pragma unroll
                for (int j = 0; j < K; ++j) {
                    const ulonglong2* wrow = (const ulonglong2*)&WS2[i * K + j][og * 8];
                    const ulonglong2 wq0 = wrow[0];
                    const ulonglong2 wq1 = wrow[1];
                    const ulonglong2 wq2 = wrow[2];
                    const ulonglong2 wq3 = wrow[3];
                    const int sx = lane + j * DIL;
                    const unsigned long long xa = pk2(XS[ri + 0][sx], XS[ri + 1][sx]);
                    const unsigned long long xb = pk2(XS[ri + 2][sx], XS[ri + 3][sx]);
                    fma2(acc[0][0], wq0.x, xa);  fma2(acc[0][1], wq0.x, xb);
                    fma2(acc[1][0], wq0.y, xa);  fma2(acc[1][1], wq0.y, xb);
                    fma2(acc[2][0], wq1.x, xa);  fma2(acc[2][1], wq1.x, xb);
                    fma2(acc[3][0], wq1.y, xa);  fma2(acc[3][1], wq1.y, xb);
                    fma2(acc[4][0], wq2.x, xa);  fma2(acc[4][1], wq2.x, xb);
                    fma2(acc[5][0], wq2.y, xa);  fma2(acc[5][1], wq2.y, xb);
                    fma2(acc[6][0], wq3.x, xa);  fma2(acc[6][1], wq3.x, xb);
                    fma2(acc[7][0], wq3.y, xa);  fma2(acc[7][1], wq3.y, xb);
                }
            }
        }
    }

    float* pb = part + (((size_t)sp * 2 + b) * O) * HWSZ;
    #pragma unroll
    for (int oc = 0; oc < 8; ++oc) {
        const int o = o0 + og * 8 + oc;
        if (o < O) {
            float r0, r1, r2, r3;
            unpk2(acc[oc][0], r0, r1);
            unpk2(acc[oc][1], r2, r3);
            float* po = pb + (size_t)o * HWSZ + h0 * 64 + lane;
            po[0]   = r0;
            po[64]  = r1;
            po[128] = r2;
            po[192] = r3;
        }
    }
}

// ---------------------------------------------------------------------------
// combine_pair: reduce NS slabs for BOTH offset channels of tap k, add bias,
// emit interleaved float2 offsets off[b][k][hw]{oy,ox}.
// grid (8, K, 2), block 128; each thread covers 4 pixels.
// ---------------------------------------------------------------------------
template<int NS>
__global__ void combine_pair(const float* __restrict__ part,
                             const float* __restrict__ bias,
                             int O, float2* __restrict__ off)
{
    const int p = blockIdx.x * 128 + threadIdx.x;   // float4 index (4 px)
    const int k = blockIdx.y;
    const int b = blockIdx.z;

    float4 vy[NS], vx[NS];
    #pragma unroll
    for (int sp = 0; sp < NS; ++sp) {
        const float4* pb = (const float4*)part + (((size_t)sp * 2 + b) * O) * 1024;
        vy[sp] = pb[(size_t)(2 * k)     * 1024 + p];
        vx[sp] = pb[(size_t)(2 * k + 1) * 1024 + p];
    }

    const float by = bias[2 * k];
    const float bx = bias[2 * k + 1];
    float4 sy = make_float4(by, by, by, by);
    float4 sx = make_float4(bx, bx, bx, bx);
    #pragma unroll
    for (int sp = 0; sp < NS; ++sp) {
        sy.x += vy[sp].x; sy.y += vy[sp].y; sy.z += vy[sp].z; sy.w += vy[sp].w;
        sx.x += vx[sp].x; sx.y += vx[sp].y; sx.z += vx[sp].z; sx.w += vx[sp].w;
    }

    float4* ob = (float4*)(off + ((size_t)b * gridDim.y + k) * HWSZ) + p * 2;
    ob[0] = make_float4(sy.x, sx.x, sy.y, sx.y);
    ob[1] = make_float4(sy.z, sx.z, sy.w, sx.w);
}

// ---------------------------------------------------------------------------
// Deformable depthwise conv over channel PAIRS. Interleaved float2 gathers
// AND interleaved float2 offsets (1 LDG.64/tap). Tap loop unrolled x4.
// Block 256 thr; grid (16, 32, 2) = 1024 blocks.
// ---------------------------------------------------------------------------
template<int KS, int DIL, int PAD>
__global__ void deform_i(const float2* __restrict__ xin, int cstride, int coffp,
                         const float2* __restrict__ off,
                         const float* __restrict__ dw,
                         float* __restrict__ out, float2* __restrict__ outi)
{
    constexpr int K = KS * KS;
    __shared__ float sdw[2][K];

    const int tid = threadIdx.x;
    const int w   = tid & 63;
    const int r   = tid >> 6;
    const int h   = blockIdx.x * 4 + r;
    const int cg  = blockIdx.y;
    const int b   = blockIdx.z;

    if (tid < 2 * K) sdw[tid / K][tid % K] = dw[(cg * 2 + tid / K) * K + tid % K];
    __syncthreads();

    const float2* xr = xin + ((size_t)b * cstride + coffp + cg) * HWSZ;
    const float2* ob = off + (size_t)b * K * HWSZ + h * WW + w;

    float acc0 = 0.f, acc1 = 0.f;

    #pragma unroll 4
    for (int kidx = 0; kidx < K; ++kidx) {
        const float2 o2 = ob[(size_t)kidx * HWSZ];
        const float py = o2.x + (float)(h - PAD + (kidx / KS) * DIL);
        const float px = o2.y + (float)(w - PAD + (kidx % KS) * DIL);
        const int   y0 = __float2int_rd(py);
        const int   x0 = __float2int_rd(px);
        const float ly = py - (float)y0;
        const float lx = px - (float)x0;

        const float hyM = ((unsigned)y0       < 64u) ? (1.f - ly) : 0.f;
        const float lyM = ((unsigned)(y0 + 1) < 64u) ? ly         : 0.f;
        const float hxM = ((unsigned)x0       < 64u) ? (1.f - lx) : 0.f;
        const float lxM = ((unsigned)(x0 + 1) < 64u) ? lx         : 0.f;

        const float w00 = hyM * hxM;
        const float w01 = hyM * lxM;
        const float w10 = lyM * hxM;
        const float w11 = lyM * lxM;

        const int i00 = (y0 * 64 + x0) & 4095;
        const int i01 = (i00 + 1)  & 4095;
        const int i10 = (i00 + 64) & 4095;
        const int i11 = (i00 + 65) & 4095;

        const float2 v00 = xr[i00];
        const float2 v01 = xr[i01];
        const float2 v10 = xr[i10];
        const float2 v11 = xr[i11];

        float va = v00.x * w00;
        va = fmaf(v01.x, w01, va);
        va = fmaf(v10.x, w10, va);
        va = fmaf(v11.x, w11, va);
        acc0 = fmaf(va, sdw[0][kidx], acc0);

        float vb = v00.y * w00;
        vb = fmaf(v01.y, w01, vb);
        vb = fmaf(v10.y, w10, vb);
        vb = fmaf(v11.y, w11, vb);
        acc1 = fmaf(vb, sdw[1][kidx], acc1);
    }

    const int p = h * WW + w;
    float* po = out + ((size_t)b * CCH + cg * 2) * HWSZ + p;
    po[0]    = acc0;
    po[HWSZ] = acc1;
    if (outi)
        outi[((size_t)b * 32 + cg) * HWSZ + p] = make_float2(acc0, acc1);
}

// ---------------------------------------------------------------------------
// 1x1 conv + gate, 2 outputs per block (R13, proven).
// grid (8, 32, 2) = 512 blocks, block 256 (512 px).
// ---------------------------------------------------------------------------
__global__ void conv1x1_gate2(const float* __restrict__ in,
                              const float* __restrict__ wv,
                              const float* __restrict__ bias,
                              const float* __restrict__ x,
                              int xcoff, float* __restrict__ out)
{
    __shared__ float2 wsm[CCH][2];
    const int tid = threadIdx.x;
    const int o0  = blockIdx.y * 2;
    const int b   = blockIdx.z;
    const int px0 = blockIdx.x * 512 + tid * 2;

    for (int idx = tid; idx < CCH * 2; idx += 256) {
        const int c = idx >> 1;
        const int o = idx & 1;
        const float w_ = wv[(o0 + o) * CCH + c];
        wsm[c][o] = make_float2(w_, w_);
    }
    __syncthreads();

    unsigned long long a0 = pk2(bias[o0],     bias[o0]);
    unsigned long long a1 = pk2(bias[o0 + 1], bias[o0 + 1]);

    const float* ib = in + (size_t)b * CCH * HWSZ + px0;
    #pragma unroll 8
    for (int c = 0; c < CCH; ++c) {
        const unsigned long long iv = *(const unsigned long long*)(ib + (size_t)c * HWSZ);
        const ulonglong2 w2 = *(const ulonglong2*)&wsm[c][0];
        fma2(a0, w2.x, iv);
        fma2(a1, w2.y, iv);
    }

    const size_t oi0 = ((size_t)b * 128 + xcoff + o0) * HWSZ + px0;
    const unsigned long long xv0 = *(const unsigned long long*)(x + oi0);
    const unsigned long long xv1 = *(const unsigned long long*)(x + oi0 + HWSZ);
    *(unsigned long long*)(out + oi0)        = mul2(a0, xv0);
    *(unsigned long long*)(out + oi0 + HWSZ) = mul2(a1, xv1);
}

// ---------------------------------------------------------------------------
extern "C" void kernel_launch(void* const* d_in, const int* in_sizes, int n_in,
                              void* d_out, int out_size)
{
    const float* x          = (const float*)d_in[0];
    const float* cv0_off_w  = (const float*)d_in[1];
    const float* cv0_off_b  = (const float*)d_in[2];
    const float* cv0_w      = (const float*)d_in[3];
    const float* cvs_off_w  = (const float*)d_in[4];
    const float* cvs_off_b  = (const float*)d_in[5];
    const float* cvs_w      = (const float*)d_in[6];
    const float* c0_off_w   = (const float*)d_in[7];
    const float* c0_off_b   = (const float*)d_in[8];
    const float* c0_w       = (const float*)d_in[9];
    const float* cs_off_w   = (const float*)d_in[10];
    const float* cs_off_b   = (const float*)d_in[11];
    const float* cs_w       = (const float*)d_in[12];
    const float* conv1_w    = (const float*)d_in[13];
    const float* conv1_b    = (const float*)d_in[14];
    const float* conv2_w    = (const float*)d_in[15];
    const float* conv2_b    = (const float*)d_in[16];
    float* out = (float*)d_out;

    static cudaStream_t s2 = nullptr;
    static cudaEvent_t evRoot = nullptr, evW = nullptr, evX = nullptr, evJoin = nullptr;
    if (!s2) {
        cudaStreamCreateWithFlags(&s2, cudaStreamNonBlocking);
        cudaEventCreateWithFlags(&evRoot, cudaEventDisableTiming);
        cudaEventCreateWithFlags(&evW,    cudaEventDisableTiming);
        cudaEventCreateWithFlags(&evX,    cudaEventDisableTiming);
        cudaEventCreateWithFlags(&evJoin, cudaEventDisableTiming);
    }

    float *offb, *tmp, *part, *wt;
    float2 *xi, *t0ai, *t0bi;
    cudaGetSymbolAddress((void**)&offb, g_off);
    cudaGetSymbolAddress((void**)&tmp,  g_tmp);
    cudaGetSymbolAddress((void**)&part, g_part);
    cudaGetSymbolAddress((void**)&wt,   g_wt);
    cudaGetSymbolAddress((void**)&xi,   g_xi);
    cudaGetSymbolAddress((void**)&t0ai, g_t0ai);
    cudaGetSymbolAddress((void**)&t0bi, g_t0bi);

    float2* off0 = (float2*)offb;                            // needs 2*25*HWSZ f2
    float2* off1 = (float2*)(offb + (size_t)2 * 100 * HWSZ); // needs 2*49*HWSZ f2
    float* t0a   = tmp;
    float* t1a   = tmp + (size_t)1 * CCH * 2 * HWSZ;
    float* t0b   = tmp + (size_t)2 * CCH * 2 * HWSZ;
    float* t1b   = tmp + (size_t)3 * CCH * 2 * HWSZ;
    float* part0 = part;
    float* part1 = part + (size_t)4 * 1024 * 1024;

    const int taps3 = 576, taps5 = 1600, taps7 = 3136;
    float* wt_cv0 = wt;
    float* wt_cvs = wt_cv0 + 18 * taps3;
    float* wt_c0  = wt_cvs + 50 * taps5;
    float* wt_cs  = wt_c0  + 50 * taps5;

    dim3 b256(256), b128(128);

    // legal fork: s2 joins capture via event recorded in origin stream FIRST
    cudaEventRecord(evRoot, 0);
    cudaStreamWaitEvent(s2, evRoot, 0);

    // parallel prologue: wtrans on s0 || xpack on s2
    const int n_all = 18 * taps3 + 50 * taps5 + 50 * taps5 + 98 * taps7;
    wtrans_all<<<(n_all + 255) / 256, b256>>>(cv0_off_w, cvs_off_w, c0_off_w, cs_off_w, wt);
    cudaEventRecord(evW, 0);
    xpack_kernel<<<dim3(16, 64, 2), b256, 0, s2>>>(x, xi);
    cudaEventRecord(evX, s2);
    cudaStreamWaitEvent(0, evX, 0);
    cudaStreamWaitEvent(s2, evW, 0);

    // ---- Branch 0 (stream 0): channels [0,64) ----
    offconv_gemm<3,1,1><<<dim3(16, 1, 2 * 8), b256>>>(x, 128, 0, wt_cv0, 18, 8, part0);
    combine_pair<8><<<dim3(8, 9, 2), b128>>>(part0, cv0_off_b, 18, off0);
    deform_i<3,1,1><<<dim3(16, 32, 2), b256>>>(xi, 64, 0, off0, cv0_w, t0a, t0ai);

    offconv_gemm<5,3,6><<<dim3(16, 2, 2 * 8), b256>>>(t0a, 64, 0, wt_cvs, 50, 8, part0);
    combine_pair<8><<<dim3(8, 25, 2), b128>>>(part0, cvs_off_b, 50, off0);
    deform_i<5,3,6><<<dim3(16, 32, 2), b256>>>(t0ai, 32, 0, off0, cvs_w, t1a, nullptr);

    conv1x1_gate2<<<dim3(8, 32, 2), b256>>>(t1a, conv1_w, conv1_b, x, 0, out);

    // ---- Branch 1 (stream s2): channels [64,128) ----
    offconv_gemm<5,1,2><<<dim3(16, 2, 2 * 8), b256, 0, s2>>>(x, 128, 64, wt_c0, 50, 8, part1);
    combine_pair<8><<<dim3(8, 25, 2), b128, 0, s2>>>(part1, c0_off_b, 50, off1);
    deform_i<5,1,2><<<dim3(16, 32, 2), b256, 0, s2>>>(xi, 64, 32, off1, c0_w, t0b, t0bi);

    offconv_gemm<7,3,9><<<dim3(16, 4, 2 * 4), b256, 0, s2>>>(t0b, 64, 0, wt_cs, 98, 4, part1);
    combine_pair<4><<<dim3(8, 49, 2), b128, 0, s2>>>(part1, cs_off_b, 98, off1);
    deform_i<7,3,9><<<dim3(16, 32, 2), b256, 0, s2>>>(t0bi, 32, 0, off1, cs_w, t1b, nullptr);

    conv1x1_gate2<<<dim3(8, 32, 2), b256, 0, s2>>>(t1b, conv2_w, conv2_b, x, 64, out);

    cudaEventRecord(evJoin, s2);
    cudaStreamWaitEvent(0, evJoin, 0);
}